// round 1
// baseline (speedup 1.0000x reference)
#include <cuda_runtime.h>
#include <cuda_bf16.h>
#include <cstdint>

// Problem constants
constexpr int Bb = 4;
constexpr int Tt = 2048;
constexpr int Dd = 2048;
constexpr int Hh = 16;
constexpr int HD = 128;
constexpr int Mrows = Bb * Tt;  // 8192
constexpr float SCALE = 0.08838834764831845f;  // 1/sqrt(128)

// Scratch (device globals; no allocation allowed)
__device__ float g_Q[(size_t)Bb * Tt * Dd];
__device__ float g_K[(size_t)Bb * Tt * Dd];
__device__ float g_V[(size_t)Bb * Tt * Dd];
__device__ float g_ctx[(size_t)Bb * Tt * Dd];

// ----------------------------------------------------------------------------
// Tiled SGEMM: C = A[M,K] * B[K,N] + bias
// 128x128 block tile, BK=16, 256 threads, 8x8 per-thread micro-tile.
// MODE 0: plain row-major output C[m*N + n]
// MODE 1: QKV scatter: output to [b, h, t, hd] layout (N==2048, BN==HD==128,
//         so each block's column range lies inside exactly one head).
// ----------------------------------------------------------------------------
template <int MODE>
__global__ __launch_bounds__(256) void sgemm128(
    const float* __restrict__ A, const float* __restrict__ Bm,
    const float* __restrict__ bias, float* __restrict__ Cout,
    int N, int K)
{
    __shared__ float As[16][132];  // stored transposed: As[k][m], padded
    __shared__ float Bs[16][132];  // Bs[k][n], padded

    const int tid = threadIdx.x;
    const int m0 = blockIdx.y * 128;
    const int n0 = blockIdx.x * 128;

    const int tm = (tid >> 4) * 8;   // 16 groups of 8 rows
    const int tn = (tid & 15) * 8;   // 16 groups of 8 cols

    float acc[8][8];
#pragma unroll
    for (int i = 0; i < 8; i++)
#pragma unroll
        for (int j = 0; j < 8; j++) acc[i][j] = 0.f;

    for (int k0 = 0; k0 < K; k0 += 16) {
        // Load A tile (128x16) transposed into As
#pragma unroll
        for (int l = 0; l < 2; l++) {
            int f = tid + l * 256;
            int r = f >> 2;
            int c = (f & 3) * 4;
            float4 v = *(const float4*)&A[(size_t)(m0 + r) * K + k0 + c];
            As[c + 0][r] = v.x;
            As[c + 1][r] = v.y;
            As[c + 2][r] = v.z;
            As[c + 3][r] = v.w;
        }
        // Load B tile (16x128) directly into Bs
#pragma unroll
        for (int l = 0; l < 2; l++) {
            int f = tid + l * 256;
            int r = f >> 5;
            int c = (f & 31) * 4;
            *(float4*)&Bs[r][c] = *(const float4*)&Bm[(size_t)(k0 + r) * N + n0 + c];
        }
        __syncthreads();

#pragma unroll
        for (int kk = 0; kk < 16; kk++) {
            float a[8], b[8];
            *(float4*)(a)     = *(float4*)&As[kk][tm];
            *(float4*)(a + 4) = *(float4*)&As[kk][tm + 4];
            *(float4*)(b)     = *(float4*)&Bs[kk][tn];
            *(float4*)(b + 4) = *(float4*)&Bs[kk][tn + 4];
#pragma unroll
            for (int i = 0; i < 8; i++)
#pragma unroll
                for (int j = 0; j < 8; j++) acc[i][j] += a[i] * b[j];
        }
        __syncthreads();
    }

    // Epilogue
    if (MODE == 0) {
#pragma unroll
        for (int i = 0; i < 8; i++) {
            size_t row = (size_t)(m0 + tm + i);
#pragma unroll
            for (int jj = 0; jj < 2; jj++) {
                float4 v;
                v.x = acc[i][jj * 4 + 0] + bias[n0 + tn + jj * 4 + 0];
                v.y = acc[i][jj * 4 + 1] + bias[n0 + tn + jj * 4 + 1];
                v.z = acc[i][jj * 4 + 2] + bias[n0 + tn + jj * 4 + 2];
                v.w = acc[i][jj * 4 + 3] + bias[n0 + tn + jj * 4 + 3];
                *(float4*)&Cout[row * N + n0 + tn + jj * 4] = v;
            }
        }
    } else {
        const int h = n0 >> 7;  // head index (BN == HD == 128)
#pragma unroll
        for (int i = 0; i < 8; i++) {
            int m = m0 + tm + i;
            int b = m >> 11;       // / T
            int t = m & 2047;      // % T
            size_t base = (((size_t)b * Hh + h) * Tt + t) * HD + tn;
#pragma unroll
            for (int jj = 0; jj < 2; jj++) {
                float4 v;
                v.x = acc[i][jj * 4 + 0] + bias[n0 + tn + jj * 4 + 0];
                v.y = acc[i][jj * 4 + 1] + bias[n0 + tn + jj * 4 + 1];
                v.z = acc[i][jj * 4 + 2] + bias[n0 + tn + jj * 4 + 2];
                v.w = acc[i][jj * 4 + 3] + bias[n0 + tn + jj * 4 + 3];
                *(float4*)&Cout[base + jj * 4] = v;
            }
        }
    }
}

// ----------------------------------------------------------------------------
// Flash attention: per (b,h), 64-query x 64-key tiles, HD=128, fp32,
// analytic causal mask, online softmax.
// Grid: (T/64 = 32, B*H = 64), 256 threads.
// ----------------------------------------------------------------------------
constexpr int QS_STRIDE = 68;   // [128][68] padded, d-major (transposed)
constexpr int SS_STRIDE = 68;   // [64][68]  S stored [k][q]
constexpr int ATTN_SMEM_FLOATS =
    128 * QS_STRIDE +   // Qs
    128 * QS_STRIDE +   // Ks
    64 * 128 +          // Vs
    64 * SS_STRIDE +    // Ss
    64 * 3 +            // rowm, rowl, corr
    512;                // red (max) + red2 (sum)
constexpr int ATTN_SMEM_BYTES = ATTN_SMEM_FLOATS * 4;

__global__ __launch_bounds__(256) void attn_kernel(
    const float* __restrict__ Qg, const float* __restrict__ Kg,
    const float* __restrict__ Vg, float* __restrict__ ctx)
{
    extern __shared__ float sm[];
    float* Qs   = sm;                         // [128][68]  Qs[d*68 + q]
    float* Ks   = Qs + 128 * QS_STRIDE;       // [128][68]  Ks[d*68 + k]
    float* Vs   = Ks + 128 * QS_STRIDE;       // [64][128]  Vs[k*128 + d]
    float* Ss   = Vs + 64 * 128;              // [64][68]   Ss[k*68 + q]
    float* rowm = Ss + 64 * SS_STRIDE;
    float* rowl = rowm + 64;
    float* corr = rowl + 64;
    float* red  = corr + 64;                  // [4][64]
    float* red2 = red + 256;                  // [4][64]

    const int tid = threadIdx.x;
    const int bh = blockIdx.y;
    const int q0 = blockIdx.x * 64;

    const float* Qp = Qg + (size_t)bh * Tt * HD;
    const float* Kp = Kg + (size_t)bh * Tt * HD;
    const float* Vp = Vg + (size_t)bh * Tt * HD;

    // Load Q tile transposed: Qs[d][q]
#pragma unroll
    for (int l = 0; l < 8; l++) {
        int f = tid + l * 256;
        int r = f >> 5;          // query row 0..63
        int c = (f & 31) * 4;    // dim 0..124
        float4 v = *(const float4*)&Qp[(size_t)(q0 + r) * HD + c];
        Qs[(c + 0) * QS_STRIDE + r] = v.x;
        Qs[(c + 1) * QS_STRIDE + r] = v.y;
        Qs[(c + 2) * QS_STRIDE + r] = v.z;
        Qs[(c + 3) * QS_STRIDE + r] = v.w;
    }
    if (tid < 64) {
        rowm[tid] = -1e30f;
        rowl[tid] = 0.f;
    }

    // Per-thread output tile: 4 rows x 8 cols
    const int tm = (tid >> 4) * 4;   // query rows
    const int tn = (tid & 15) * 8;   // head-dim cols
    float acc[4][8];
#pragma unroll
    for (int i = 0; i < 4; i++)
#pragma unroll
        for (int j = 0; j < 8; j++) acc[i][j] = 0.f;

    // S-phase thread mapping: 4x4 micro-tile
    const int stm = (tid >> 4) * 4;  // query
    const int stn = (tid & 15) * 4;  // key

    // Softmax mapping
    const int sg = tid >> 6;   // 0..3
    const int sq = tid & 63;   // query column

    for (int kt = 0; kt <= blockIdx.x; kt++) {
        const int k0 = kt * 64;
        // Load K tile transposed, V tile direct
#pragma unroll
        for (int l = 0; l < 8; l++) {
            int f = tid + l * 256;
            int r = f >> 5;
            int c = (f & 31) * 4;
            float4 kv = *(const float4*)&Kp[(size_t)(k0 + r) * HD + c];
            Ks[(c + 0) * QS_STRIDE + r] = kv.x;
            Ks[(c + 1) * QS_STRIDE + r] = kv.y;
            Ks[(c + 2) * QS_STRIDE + r] = kv.z;
            Ks[(c + 3) * QS_STRIDE + r] = kv.w;
            *(float4*)&Vs[r * 128 + c] = *(const float4*)&Vp[(size_t)(k0 + r) * HD + c];
        }
        __syncthreads();

        // S = Q K^T (64x64x128)
        float s[4][4];
#pragma unroll
        for (int i = 0; i < 4; i++)
#pragma unroll
            for (int j = 0; j < 4; j++) s[i][j] = 0.f;
        for (int d = 0; d < 128; d++) {
            float4 qa = *(float4*)&Qs[d * QS_STRIDE + stm];
            float4 kb = *(float4*)&Ks[d * QS_STRIDE + stn];
            float aq[4] = {qa.x, qa.y, qa.z, qa.w};
            float bk[4] = {kb.x, kb.y, kb.z, kb.w};
#pragma unroll
            for (int i = 0; i < 4; i++)
#pragma unroll
                for (int j = 0; j < 4; j++) s[i][j] += aq[i] * bk[j];
        }
        // scale + causal mask, store transposed Ss[k][q]
#pragma unroll
        for (int i = 0; i < 4; i++) {
            int qg = q0 + stm + i;
#pragma unroll
            for (int j = 0; j < 4; j++) {
                int kg = k0 + stn + j;
                float v = s[i][j] * SCALE;
                if (kg > qg) v = -1e30f;
                Ss[(stn + j) * SS_STRIDE + (stm + i)] = v;
            }
        }
        __syncthreads();

        // Online softmax: 4 threads per query column
        float pm = -1e30f;
        for (int kk = sg * 16; kk < sg * 16 + 16; kk++)
            pm = fmaxf(pm, Ss[kk * SS_STRIDE + sq]);
        red[sg * 64 + sq] = pm;
        __syncthreads();

        float mt = fmaxf(fmaxf(red[sq], red[64 + sq]),
                         fmaxf(red[128 + sq], red[192 + sq]));
        float mo = rowm[sq];
        float mn = fmaxf(mo, mt);
        float ps = 0.f;
        for (int kk = sg * 16; kk < sg * 16 + 16; kk++) {
            float p = __expf(Ss[kk * SS_STRIDE + sq] - mn);
            Ss[kk * SS_STRIDE + sq] = p;
            ps += p;
        }
        red2[sg * 64 + sq] = ps;
        __syncthreads();

        if (sg == 0) {
            float ls = red2[sq] + red2[64 + sq] + red2[128 + sq] + red2[192 + sq];
            float cf = __expf(mo - mn);
            corr[sq] = cf;
            rowm[sq] = mn;
            rowl[sq] = rowl[sq] * cf + ls;
        }
        __syncthreads();

        // O += P V  (with rescale by corr)
#pragma unroll
        for (int i = 0; i < 4; i++) {
            float cf = corr[tm + i];
#pragma unroll
            for (int j = 0; j < 8; j++) acc[i][j] *= cf;
        }
        for (int kk = 0; kk < 64; kk++) {
            float4 p4 = *(float4*)&Ss[kk * SS_STRIDE + tm];
            float4 v0 = *(float4*)&Vs[kk * 128 + tn];
            float4 v1 = *(float4*)&Vs[kk * 128 + tn + 4];
            float pv[4] = {p4.x, p4.y, p4.z, p4.w};
            float vv[8] = {v0.x, v0.y, v0.z, v0.w, v1.x, v1.y, v1.z, v1.w};
#pragma unroll
            for (int i = 0; i < 4; i++)
#pragma unroll
                for (int j = 0; j < 8; j++) acc[i][j] += pv[i] * vv[j];
        }
        __syncthreads();
    }

    // Normalize and write ctx in [b, t, h*HD + d] layout
    const int b = bh >> 4;
    const int h = bh & 15;
#pragma unroll
    for (int i = 0; i < 4; i++) {
        float inv = 1.f / rowl[tm + i];
        int t = q0 + tm + i;
        size_t base = ((size_t)b * Tt + t) * Dd + h * HD + tn;
        float4 o0, o1;
        o0.x = acc[i][0] * inv; o0.y = acc[i][1] * inv;
        o0.z = acc[i][2] * inv; o0.w = acc[i][3] * inv;
        o1.x = acc[i][4] * inv; o1.y = acc[i][5] * inv;
        o1.z = acc[i][6] * inv; o1.w = acc[i][7] * inv;
        *(float4*)&ctx[base] = o0;
        *(float4*)&ctx[base + 4] = o1;
    }
}

// ----------------------------------------------------------------------------
extern "C" void kernel_launch(void* const* d_in, const int* in_sizes, int n_in,
                              void* d_out, int out_size)
{
    const float* X   = (const float*)d_in[0];
    // d_in[1] = mask (exactly causal; applied analytically in attn_kernel)
    const float* wq  = (const float*)d_in[2];
    const float* bq  = (const float*)d_in[3];
    const float* wk  = (const float*)d_in[4];
    const float* bk  = (const float*)d_in[5];
    const float* wv  = (const float*)d_in[6];
    const float* bv  = (const float*)d_in[7];
    const float* wo  = (const float*)d_in[8];
    const float* bo  = (const float*)d_in[9];
    float* out = (float*)d_out;

    float *Qb, *Kb, *Vb, *Cb;
    cudaGetSymbolAddress((void**)&Qb, g_Q);
    cudaGetSymbolAddress((void**)&Kb, g_K);
    cudaGetSymbolAddress((void**)&Vb, g_V);
    cudaGetSymbolAddress((void**)&Cb, g_ctx);

    cudaFuncSetAttribute(attn_kernel,
                         cudaFuncAttributeMaxDynamicSharedMemorySize,
                         ATTN_SMEM_BYTES);

    dim3 ggrid(Dd / 128, Mrows / 128);  // (16, 64)
    sgemm128<1><<<ggrid, 256>>>(X, wq, bq, Qb, Dd, Dd);
    sgemm128<1><<<ggrid, 256>>>(X, wk, bk, Kb, Dd, Dd);
    sgemm128<1><<<ggrid, 256>>>(X, wv, bv, Vb, Dd, Dd);

    dim3 agrid(Tt / 64, Bb * Hh);       // (32, 64)
    attn_kernel<<<agrid, 256, ATTN_SMEM_BYTES>>>(Qb, Kb, Vb, Cb);

    sgemm128<0><<<ggrid, 256>>>(Cb, wo, bo, out, Dd, Dd);
}

// round 12
// speedup vs baseline: 5.0333x; 5.0333x over previous
#include <cuda_runtime.h>
#include <cuda_bf16.h>
#include <cstdint>

// ---------------------------------------------------------------------------
// Problem constants
// ---------------------------------------------------------------------------
constexpr int Bb = 4;
constexpr int Tt = 2048;
constexpr int Dd = 2048;
constexpr int Hh = 16;
constexpr int HD = 128;
constexpr int Mrows = Bb * Tt;  // 8192
constexpr float SCALE = 0.08838834764831845f;  // 1/sqrt(128)

// Scratch (device globals; no allocation allowed)
__device__ float g_Q[(size_t)Bb * Tt * Dd];
__device__ float g_K[(size_t)Bb * Tt * Dd];
__device__ float g_V[(size_t)Bb * Tt * Dd];
__device__ float g_ctx[(size_t)Bb * Tt * Dd];

// ---------------------------------------------------------------------------
// tf32 helpers (mma.sync path — sm_80+ features, legal at plain sm_103 target)
// ---------------------------------------------------------------------------
__device__ __forceinline__ uint32_t f2tf32(float x) {
    uint32_t r;
    asm("cvt.rna.tf32.f32 %0, %1;" : "=r"(r) : "f"(x));
    return r;
}

__device__ __forceinline__ void mma_16n8k8_tf32(
    float c[4], const uint32_t a[4], const uint32_t b[2])
{
    asm volatile(
        "mma.sync.aligned.m16n8k8.row.col.f32.tf32.tf32.f32 "
        "{%0,%1,%2,%3}, {%4,%5,%6,%7}, {%8,%9}, {%0,%1,%2,%3};"
        : "+f"(c[0]), "+f"(c[1]), "+f"(c[2]), "+f"(c[3])
        : "r"(a[0]), "r"(a[1]), "r"(a[2]), "r"(a[3]),
          "r"(b[0]), "r"(b[1]));
}

// ---------------------------------------------------------------------------
// tf32 mma.sync GEMM: C[M,N] = A[M,K] @ W[K,N] + bias  (unchanged from R5)
// ---------------------------------------------------------------------------
constexpr int GBM = 128, GBN = 128, GBK = 32, GKD = 2048;
constexpr int KT_ITERS = GKD / GBK;  // 64
constexpr int AS_STRIDE = 36;    // 36 mod 32 == 4  -> conflict-free A frags
constexpr int BS_STRIDE = 136;   // 136 mod 32 == 8 -> conflict-free B frags

template <int MODE>
__global__ __launch_bounds__(256) void tc_gemm(
    const float* __restrict__ A, const float* __restrict__ W,
    const float* __restrict__ bias, float* __restrict__ Cout)
{
    __shared__ float As[GBM][AS_STRIDE];   // [m][k]  128x36
    __shared__ float Bs[GBK][BS_STRIDE];   // [k][n]  32x136

    const int tid  = threadIdx.x;
    const int lane = tid & 31;
    const int wid  = tid >> 5;
    const int gid  = lane >> 2;   // 0..7
    const int tig  = lane & 3;    // 0..3
    const int wm   = (wid >> 2) * 64;
    const int wn   = (wid & 3) * 32;
    const int m0   = blockIdx.y * GBM;
    const int n0   = blockIdx.x * GBN;

    float acc[4][4][4];
#pragma unroll
    for (int i = 0; i < 4; i++)
#pragma unroll
        for (int j = 0; j < 4; j++)
#pragma unroll
            for (int q = 0; q < 4; q++) acc[i][j][q] = 0.f;

    float4 av[4], bv[4];

    auto ldg_tile = [&](int kt, float4 av_[4], float4 bv_[4]) {
        const int k0 = kt * GBK;
#pragma unroll
        for (int l = 0; l < 4; l++) {
            int f = tid + l * 256;
            int r = f >> 3, c = f & 7;
            av_[l] = *(const float4*)&A[(size_t)(m0 + r) * GKD + k0 + c * 4];
        }
#pragma unroll
        for (int l = 0; l < 4; l++) {
            int f = tid + l * 256;
            int r = f >> 5, c = f & 31;
            bv_[l] = *(const float4*)&W[(size_t)(k0 + r) * Dd + n0 + c * 4];
        }
    };

    auto sts_tile = [&](const float4 av_[4], const float4 bv_[4]) {
#pragma unroll
        for (int l = 0; l < 4; l++) {
            int f = tid + l * 256;
            int r = f >> 3, c = f & 7;
            uint4 t;
            t.x = f2tf32(av_[l].x); t.y = f2tf32(av_[l].y);
            t.z = f2tf32(av_[l].z); t.w = f2tf32(av_[l].w);
            *(uint4*)&As[r][c * 4] = t;
        }
#pragma unroll
        for (int l = 0; l < 4; l++) {
            int f = tid + l * 256;
            int r = f >> 5, c = f & 31;
            uint4 t;
            t.x = f2tf32(bv_[l].x); t.y = f2tf32(bv_[l].y);
            t.z = f2tf32(bv_[l].z); t.w = f2tf32(bv_[l].w);
            *(uint4*)&Bs[r][c * 4] = t;
        }
    };

    ldg_tile(0, av, bv);
    sts_tile(av, bv);
    __syncthreads();

#pragma unroll 1
    for (int kt = 0; kt < KT_ITERS; kt++) {
        float4 av2[4], bv2[4];
        if (kt + 1 < KT_ITERS) ldg_tile(kt + 1, av2, bv2);

#pragma unroll
        for (int ks = 0; ks < 4; ks++) {
            const int kk = ks * 8;
            uint32_t af[4][4];
#pragma unroll
            for (int mt = 0; mt < 4; mt++) {
                int row = wm + mt * 16 + gid;
                af[mt][0] = __float_as_uint(As[row][kk + tig]);
                af[mt][1] = __float_as_uint(As[row + 8][kk + tig]);
                af[mt][2] = __float_as_uint(As[row][kk + tig + 4]);
                af[mt][3] = __float_as_uint(As[row + 8][kk + tig + 4]);
            }
            uint32_t bf[4][2];
#pragma unroll
            for (int nt = 0; nt < 4; nt++) {
                int col = wn + nt * 8 + gid;
                bf[nt][0] = __float_as_uint(Bs[kk + tig][col]);
                bf[nt][1] = __float_as_uint(Bs[kk + tig + 4][col]);
            }
#pragma unroll
            for (int mt = 0; mt < 4; mt++)
#pragma unroll
                for (int nt = 0; nt < 4; nt++)
                    mma_16n8k8_tf32(acc[mt][nt], af[mt], bf[nt]);
        }

        if (kt + 1 < KT_ITERS) {
            __syncthreads();
            sts_tile(av2, bv2);
            __syncthreads();
        }
    }

#pragma unroll
    for (int mt = 0; mt < 4; mt++) {
#pragma unroll
        for (int nt = 0; nt < 4; nt++) {
            int row = m0 + wm + mt * 16 + gid;
            int col = n0 + wn + nt * 8 + tig * 2;
            float bx = bias[col], by = bias[col + 1];
            float2 lo = {acc[mt][nt][0] + bx, acc[mt][nt][1] + by};
            float2 hi = {acc[mt][nt][2] + bx, acc[mt][nt][3] + by};
            if (MODE == 0) {
                *(float2*)&Cout[(size_t)row * Dd + col] = lo;
                *(float2*)&Cout[(size_t)(row + 8) * Dd + col] = hi;
            } else {
                const int h = col >> 7, hd = col & 127;
                int b = row >> 11, t = row & 2047;
                *(float2*)&Cout[(((size_t)b * Hh + h) * Tt + t) * HD + hd] = lo;
                b = (row + 8) >> 11; t = (row + 8) & 2047;
                *(float2*)&Cout[(((size_t)b * Hh + h) * Tt + t) * HD + hd] = hi;
            }
        }
    }
}

// ---------------------------------------------------------------------------
// Flash attention, tf32 mma.sync version.
// Per (b,h): 64-query blocks, 64-key tiles, HD=128. 256 threads = 8 warps.
// S phase: warp (wid>>1, wid&1) computes S[16 x 32] of the 64x64 tile.
// PV phase: same rows, warp covers 64 d-columns ((wid&1)*64).
// Layouts: Qs[q][d] str132, Ks[key][d] str132, Vs[key][d] str136, Ss[k][q] str68.
// ---------------------------------------------------------------------------
constexpr int QS2 = 132;
constexpr int KS2 = 132;
constexpr int VS2 = 136;
constexpr int SS2 = 68;
constexpr int ATTN_SMEM_FLOATS =
    64 * QS2 + 64 * KS2 + 64 * VS2 + 64 * SS2 + 64 * 3 + 512;
constexpr int ATTN_SMEM_BYTES = ATTN_SMEM_FLOATS * 4;  // ~122.6 KB

__global__ __launch_bounds__(256) void attn_kernel(
    const float* __restrict__ Qg, const float* __restrict__ Kg,
    const float* __restrict__ Vg, float* __restrict__ ctx)
{
    extern __shared__ float sm[];
    float* Qs   = sm;                 // [64][132]
    float* Ks   = Qs + 64 * QS2;      // [64][132]
    float* Vs   = Ks + 64 * KS2;      // [64][136]
    float* Ss   = Vs + 64 * VS2;      // [64][68]  S/P stored [k][q]
    float* rowm = Ss + 64 * SS2;
    float* rowl = rowm + 64;
    float* corr = rowl + 64;
    float* red  = corr + 64;          // [4][64]
    float* red2 = red + 256;          // [4][64]

    const int tid  = threadIdx.x;
    const int lane = tid & 31;
    const int wid  = tid >> 5;
    const int gid  = lane >> 2;
    const int tig  = lane & 3;
    const int sm_r = (wid >> 1) * 16;  // S/PV row group
    const int sm_c = (wid & 1) * 32;   // S col group
    const int pv_c = (wid & 1) * 64;   // PV d-col group
    const int bh = blockIdx.y;
    const int q0 = blockIdx.x * 64;

    const float* Qp = Qg + (size_t)bh * Tt * HD;
    const float* Kp = Kg + (size_t)bh * Tt * HD;
    const float* Vp = Vg + (size_t)bh * Tt * HD;

    // Load Q tile [64][128] -> Qs[q][d] (tf32-rounded)
#pragma unroll
    for (int l = 0; l < 8; l++) {
        int f = tid + l * 256;
        int r = f >> 5;
        int c = (f & 31) * 4;
        float4 v = *(const float4*)&Qp[(size_t)(q0 + r) * HD + c];
        uint4 t;
        t.x = f2tf32(v.x); t.y = f2tf32(v.y);
        t.z = f2tf32(v.z); t.w = f2tf32(v.w);
        *(uint4*)&Qs[r * QS2 + c] = t;
    }
    if (tid < 64) {
        rowm[tid] = -1e30f;
        rowl[tid] = 0.f;
    }

    // softmax mapping
    const int sg = tid >> 6;
    const int sq = tid & 63;

    float oacc[8][4];
#pragma unroll
    for (int i = 0; i < 8; i++)
#pragma unroll
        for (int q = 0; q < 4; q++) oacc[i][q] = 0.f;

#pragma unroll 1
    for (int kt = 0; kt <= blockIdx.x; kt++) {
        const int k0 = kt * 64;
        // Load K, V tiles [64][128] natural layout (coalesced, no transpose)
#pragma unroll
        for (int l = 0; l < 8; l++) {
            int f = tid + l * 256;
            int r = f >> 5;
            int c = (f & 31) * 4;
            float4 kv = *(const float4*)&Kp[(size_t)(k0 + r) * HD + c];
            uint4 tk;
            tk.x = f2tf32(kv.x); tk.y = f2tf32(kv.y);
            tk.z = f2tf32(kv.z); tk.w = f2tf32(kv.w);
            *(uint4*)&Ks[r * KS2 + c] = tk;
            float4 vv = *(const float4*)&Vp[(size_t)(k0 + r) * HD + c];
            uint4 tv;
            tv.x = f2tf32(vv.x); tv.y = f2tf32(vv.y);
            tv.z = f2tf32(vv.z); tv.w = f2tf32(vv.w);
            *(uint4*)&Vs[r * VS2 + c] = tv;
        }
        __syncthreads();

        // ---- S = Q K^T (warp: 16 rows x 32 cols, K-loop over d=128) ----
        float sacc[4][4];
#pragma unroll
        for (int nt = 0; nt < 4; nt++)
#pragma unroll
            for (int q = 0; q < 4; q++) sacc[nt][q] = 0.f;

#pragma unroll
        for (int ks = 0; ks < 16; ks++) {
            const int kk = ks * 8;
            uint32_t af[4];
            const int row = sm_r + gid;
            af[0] = __float_as_uint(Qs[row * QS2 + kk + tig]);
            af[1] = __float_as_uint(Qs[(row + 8) * QS2 + kk + tig]);
            af[2] = __float_as_uint(Qs[row * QS2 + kk + tig + 4]);
            af[3] = __float_as_uint(Qs[(row + 8) * QS2 + kk + tig + 4]);
#pragma unroll
            for (int nt = 0; nt < 4; nt++) {
                const int col = sm_c + nt * 8 + gid;  // key index
                uint32_t bf[2];
                bf[0] = __float_as_uint(Ks[col * KS2 + kk + tig]);
                bf[1] = __float_as_uint(Ks[col * KS2 + kk + tig + 4]);
                mma_16n8k8_tf32(sacc[nt], af, bf);
            }
        }
        // scale + causal mask, store transposed into Ss[k][q]
#pragma unroll
        for (int nt = 0; nt < 4; nt++) {
            const int kb = sm_c + nt * 8 + 2 * tig;
            const int kg = k0 + kb;
            const int qg = q0 + sm_r + gid;
            float v0 = sacc[nt][0] * SCALE; if (kg > qg)        v0 = -1e30f;
            float v1 = sacc[nt][1] * SCALE; if (kg + 1 > qg)    v1 = -1e30f;
            float v2 = sacc[nt][2] * SCALE; if (kg > qg + 8)    v2 = -1e30f;
            float v3 = sacc[nt][3] * SCALE; if (kg + 1 > qg + 8) v3 = -1e30f;
            Ss[kb * SS2 + sm_r + gid]           = v0;
            Ss[(kb + 1) * SS2 + sm_r + gid]     = v1;
            Ss[kb * SS2 + sm_r + gid + 8]       = v2;
            Ss[(kb + 1) * SS2 + sm_r + gid + 8] = v3;
        }
        __syncthreads();

        // ---- online softmax (identical logic to R1) ----
        float pm = -1e30f;
        for (int kk = sg * 16; kk < sg * 16 + 16; kk++)
            pm = fmaxf(pm, Ss[kk * SS2 + sq]);
        red[sg * 64 + sq] = pm;
        __syncthreads();

        float mt = fmaxf(fmaxf(red[sq], red[64 + sq]),
                         fmaxf(red[128 + sq], red[192 + sq]));
        float mo = rowm[sq];
        float mn = fmaxf(mo, mt);
        float ps = 0.f;
        for (int kk = sg * 16; kk < sg * 16 + 16; kk++) {
            float p = __expf(Ss[kk * SS2 + sq] - mn);
            Ss[kk * SS2 + sq] = p;
            ps += p;
        }
        red2[sg * 64 + sq] = ps;
        __syncthreads();

        if (sg == 0) {
            float ls = red2[sq] + red2[64 + sq] + red2[128 + sq] + red2[192 + sq];
            float cf = __expf(mo - mn);
            corr[sq] = cf;
            rowm[sq] = mn;
            rowl[sq] = rowl[sq] * cf + ls;
        }
        __syncthreads();

        // ---- O += P V  (warp: 16 rows x 64 d-cols, K-loop over keys=64) ----
        {
            const float cf0 = corr[sm_r + gid];
            const float cf1 = corr[sm_r + gid + 8];
#pragma unroll
            for (int nt = 0; nt < 8; nt++) {
                oacc[nt][0] *= cf0; oacc[nt][1] *= cf0;
                oacc[nt][2] *= cf1; oacc[nt][3] *= cf1;
            }
        }
#pragma unroll
        for (int ks = 0; ks < 8; ks++) {
            const int kk = ks * 8;
            uint32_t af[4];
            af[0] = __float_as_uint(Ss[(kk + tig) * SS2 + sm_r + gid]);
            af[1] = __float_as_uint(Ss[(kk + tig) * SS2 + sm_r + gid + 8]);
            af[2] = __float_as_uint(Ss[(kk + tig + 4) * SS2 + sm_r + gid]);
            af[3] = __float_as_uint(Ss[(kk + tig + 4) * SS2 + sm_r + gid + 8]);
#pragma unroll
            for (int nt = 0; nt < 8; nt++) {
                const int col = pv_c + nt * 8 + gid;  // d index
                uint32_t bf[2];
                bf[0] = __float_as_uint(Vs[(kk + tig) * VS2 + col]);
                bf[1] = __float_as_uint(Vs[(kk + tig + 4) * VS2 + col]);
                mma_16n8k8_tf32(oacc[nt], af, bf);
            }
        }
        __syncthreads();
    }

    // ---- epilogue: normalize, write ctx[b, t, h*HD + d] ----
    const int b = bh >> 4;
    const int h = bh & 15;
    const float inv0 = 1.f / rowl[sm_r + gid];
    const float inv1 = 1.f / rowl[sm_r + gid + 8];
    const int t0 = q0 + sm_r + gid;
    const int t1 = t0 + 8;
#pragma unroll
    for (int nt = 0; nt < 8; nt++) {
        const int d = pv_c + nt * 8 + tig * 2;
        float2 lo = {oacc[nt][0] * inv0, oacc[nt][1] * inv0};
        float2 hi = {oacc[nt][2] * inv1, oacc[nt][3] * inv1};
        *(float2*)&ctx[((size_t)b * Tt + t0) * Dd + h * HD + d] = lo;
        *(float2*)&ctx[((size_t)b * Tt + t1) * Dd + h * HD + d] = hi;
    }
}

// ---------------------------------------------------------------------------
extern "C" void kernel_launch(void* const* d_in, const int* in_sizes, int n_in,
                              void* d_out, int out_size)
{
    const float* X   = (const float*)d_in[0];
    // d_in[1] = mask (exactly causal; applied analytically)
    const float* wq  = (const float*)d_in[2];
    const float* bq  = (const float*)d_in[3];
    const float* wk  = (const float*)d_in[4];
    const float* bk  = (const float*)d_in[5];
    const float* wv  = (const float*)d_in[6];
    const float* bv  = (const float*)d_in[7];
    const float* wo  = (const float*)d_in[8];
    const float* bo  = (const float*)d_in[9];
    float* out = (float*)d_out;

    float *Qb, *Kb, *Vb, *Cb;
    cudaGetSymbolAddress((void**)&Qb, g_Q);
    cudaGetSymbolAddress((void**)&Kb, g_K);
    cudaGetSymbolAddress((void**)&Vb, g_V);
    cudaGetSymbolAddress((void**)&Cb, g_ctx);

    cudaFuncSetAttribute(attn_kernel,
                         cudaFuncAttributeMaxDynamicSharedMemorySize,
                         ATTN_SMEM_BYTES);

    dim3 ggrid(Dd / GBN, Mrows / GBM);  // (16, 64)

    tc_gemm<1><<<ggrid, 256>>>(X, wq, bq, Qb);
    tc_gemm<1><<<ggrid, 256>>>(X, wk, bk, Kb);
    tc_gemm<1><<<ggrid, 256>>>(X, wv, bv, Vb);

    dim3 agrid(Tt / 64, Bb * Hh);       // (32, 64)
    attn_kernel<<<agrid, 256, ATTN_SMEM_BYTES>>>(Qb, Kb, Vb, Cb);

    tc_gemm<0><<<ggrid, 256>>>(Cb, wo, bo, out);
}

// round 15
// speedup vs baseline: 5.7138x; 1.1352x over previous
#include <cuda_runtime.h>
#include <cuda_bf16.h>
#include <cstdint>

// ---------------------------------------------------------------------------
// Problem constants
// ---------------------------------------------------------------------------
constexpr int Bb = 4;
constexpr int Tt = 2048;
constexpr int Dd = 2048;
constexpr int Hh = 16;
constexpr int HD = 128;
constexpr int Mrows = Bb * Tt;  // 8192
constexpr float SCALE = 0.08838834764831845f;  // 1/sqrt(128)

// Scratch (device globals; no allocation allowed)
__device__ float g_Q[(size_t)Bb * Tt * Dd];
__device__ float g_K[(size_t)Bb * Tt * Dd];
__device__ float g_V[(size_t)Bb * Tt * Dd];
__device__ float g_ctx[(size_t)Bb * Tt * Dd];

// ---------------------------------------------------------------------------
// tf32 helpers
// ---------------------------------------------------------------------------
__device__ __forceinline__ uint32_t f2tf32(float x) {
    uint32_t r;
    asm("cvt.rna.tf32.f32 %0, %1;" : "=r"(r) : "f"(x));
    return r;
}

__device__ __forceinline__ void mma_16n8k8_tf32(
    float c[4], const uint32_t a[4], const uint32_t b[2])
{
    asm volatile(
        "mma.sync.aligned.m16n8k8.row.col.f32.tf32.tf32.f32 "
        "{%0,%1,%2,%3}, {%4,%5,%6,%7}, {%8,%9}, {%0,%1,%2,%3};"
        : "+f"(c[0]), "+f"(c[1]), "+f"(c[2]), "+f"(c[3])
        : "r"(a[0]), "r"(a[1]), "r"(a[2]), "r"(a[3]),
          "r"(b[0]), "r"(b[1]));
}

// ---------------------------------------------------------------------------
// tf32 mma.sync GEMM: C[M,N] = A[M,K] @ W[K,N] + bias
// Block 128x128x32, 256 threads = 8 warps (2x4), warp = 64x32.
// Double-buffered smem, ONE __syncthreads per K-iteration.
// ---------------------------------------------------------------------------
constexpr int GBM = 128, GBN = 128, GBK = 32, GKD = 2048;
constexpr int KT_ITERS = GKD / GBK;  // 64
constexpr int AS_STRIDE = 36;
constexpr int BS_STRIDE = 136;
constexpr int AS_TILE = GBM * AS_STRIDE;   // 4608 floats
constexpr int BS_TILE = GBK * BS_STRIDE;   // 4352 floats
constexpr int GSMEM2 = (2 * AS_TILE + 2 * BS_TILE) * 4;  // 71680 B

template <int MODE>
__global__ __launch_bounds__(256) void tc_gemm(
    const float* __restrict__ A, const float* __restrict__ W,
    const float* __restrict__ bias, float* __restrict__ Cout)
{
    extern __shared__ float gsm[];
    float* Asb = gsm;                     // [2][128][36]
    float* Bsb = gsm + 2 * AS_TILE;       // [2][32][136]

    const int tid  = threadIdx.x;
    const int lane = tid & 31;
    const int wid  = tid >> 5;
    const int gid  = lane >> 2;
    const int tig  = lane & 3;
    const int wm   = (wid >> 2) * 64;
    const int wn   = (wid & 3) * 32;
    const int m0   = blockIdx.y * GBM;
    const int n0   = blockIdx.x * GBN;

    float acc[4][4][4];
#pragma unroll
    for (int i = 0; i < 4; i++)
#pragma unroll
        for (int j = 0; j < 4; j++)
#pragma unroll
            for (int q = 0; q < 4; q++) acc[i][j][q] = 0.f;

    float4 av[4], bv[4];

    auto ldg_tile = [&](int kt) {
        const int k0 = kt * GBK;
#pragma unroll
        for (int l = 0; l < 4; l++) {
            int f = tid + l * 256;
            int r = f >> 3, c = f & 7;
            av[l] = *(const float4*)&A[(size_t)(m0 + r) * GKD + k0 + c * 4];
        }
#pragma unroll
        for (int l = 0; l < 4; l++) {
            int f = tid + l * 256;
            int r = f >> 5, c = f & 31;
            bv[l] = *(const float4*)&W[(size_t)(k0 + r) * Dd + n0 + c * 4];
        }
    };

    auto sts_tile = [&](int buf) {
        float* As = Asb + buf * AS_TILE;
        float* Bs = Bsb + buf * BS_TILE;
#pragma unroll
        for (int l = 0; l < 4; l++) {
            int f = tid + l * 256;
            int r = f >> 3, c = f & 7;
            uint4 t;
            t.x = f2tf32(av[l].x); t.y = f2tf32(av[l].y);
            t.z = f2tf32(av[l].z); t.w = f2tf32(av[l].w);
            *(uint4*)&As[r * AS_STRIDE + c * 4] = t;
        }
#pragma unroll
        for (int l = 0; l < 4; l++) {
            int f = tid + l * 256;
            int r = f >> 5, c = f & 31;
            uint4 t;
            t.x = f2tf32(bv[l].x); t.y = f2tf32(bv[l].y);
            t.z = f2tf32(bv[l].z); t.w = f2tf32(bv[l].w);
            *(uint4*)&Bs[r * BS_STRIDE + c * 4] = t;
        }
    };

    ldg_tile(0);
    sts_tile(0);
    __syncthreads();

#pragma unroll 1
    for (int kt = 0; kt < KT_ITERS; kt++) {
        const int buf = kt & 1;
        const float* As = Asb + buf * AS_TILE;
        const float* Bs = Bsb + buf * BS_TILE;
        if (kt + 1 < KT_ITERS) ldg_tile(kt + 1);  // in flight during MMAs

#pragma unroll
        for (int ks = 0; ks < 4; ks++) {
            const int kk = ks * 8;
            uint32_t af[4][4];
#pragma unroll
            for (int mt = 0; mt < 4; mt++) {
                int row = wm + mt * 16 + gid;
                af[mt][0] = __float_as_uint(As[row * AS_STRIDE + kk + tig]);
                af[mt][1] = __float_as_uint(As[(row + 8) * AS_STRIDE + kk + tig]);
                af[mt][2] = __float_as_uint(As[row * AS_STRIDE + kk + tig + 4]);
                af[mt][3] = __float_as_uint(As[(row + 8) * AS_STRIDE + kk + tig + 4]);
            }
            uint32_t bf[4][2];
#pragma unroll
            for (int nt = 0; nt < 4; nt++) {
                int col = wn + nt * 8 + gid;
                bf[nt][0] = __float_as_uint(Bs[(kk + tig) * BS_STRIDE + col]);
                bf[nt][1] = __float_as_uint(Bs[(kk + tig + 4) * BS_STRIDE + col]);
            }
#pragma unroll
            for (int mt = 0; mt < 4; mt++)
#pragma unroll
                for (int nt = 0; nt < 4; nt++)
                    mma_16n8k8_tf32(acc[mt][nt], af[mt], bf[nt]);
        }

        if (kt + 1 < KT_ITERS) {
            sts_tile(buf ^ 1);   // other buffer: safe, last read at kt-1
            __syncthreads();
        }
    }

#pragma unroll
    for (int mt = 0; mt < 4; mt++) {
#pragma unroll
        for (int nt = 0; nt < 4; nt++) {
            int row = m0 + wm + mt * 16 + gid;
            int col = n0 + wn + nt * 8 + tig * 2;
            float bx = bias[col], by = bias[col + 1];
            float2 lo = {acc[mt][nt][0] + bx, acc[mt][nt][1] + by};
            float2 hi = {acc[mt][nt][2] + bx, acc[mt][nt][3] + by};
            if (MODE == 0) {
                *(float2*)&Cout[(size_t)row * Dd + col] = lo;
                *(float2*)&Cout[(size_t)(row + 8) * Dd + col] = hi;
            } else {
                const int h = col >> 7, hd = col & 127;
                int b = row >> 11, t = row & 2047;
                *(float2*)&Cout[(((size_t)b * Hh + h) * Tt + t) * HD + hd] = lo;
                b = (row + 8) >> 11; t = (row + 8) & 2047;
                *(float2*)&Cout[(((size_t)b * Hh + h) * Tt + t) * HD + hd] = hi;
            }
        }
    }
}

// ---------------------------------------------------------------------------
// Flash attention, tf32 mma.sync, 128-query blocks x 64-key tiles.
// 256 threads = 8 warps; warp w owns 16 query rows (sm_r = w*16) and computes
// S[16 x 64] (all keys) and O[16 x 128] (all d).
// ---------------------------------------------------------------------------
constexpr int AQ = 128;
constexpr int QS2 = 132;
constexpr int KS2 = 132;
constexpr int VS2 = 136;
constexpr int SS2 = 132;   // Ss[k][q], q up to 128
constexpr int ATTN_SMEM_FLOATS =
    AQ * QS2 + 64 * KS2 + 64 * VS2 + 64 * SS2 + AQ * 3 + 2 * AQ * 2;
constexpr int ATTN_SMEM_BYTES = ATTN_SMEM_FLOATS * 4;  // ~169.6 KB

__global__ __launch_bounds__(256) void attn_kernel(
    const float* __restrict__ Qg, const float* __restrict__ Kg,
    const float* __restrict__ Vg, float* __restrict__ ctx)
{
    extern __shared__ float sm[];
    float* Qs   = sm;                 // [128][132]
    float* Ks   = Qs + AQ * QS2;      // [64][132]
    float* Vs   = Ks + 64 * KS2;      // [64][136]
    float* Ss   = Vs + 64 * VS2;      // [64][132]  S/P stored [k][q]
    float* rowm = Ss + 64 * SS2;      // [128]
    float* rowl = rowm + AQ;
    float* corr = rowl + AQ;
    float* red  = corr + AQ;          // [2][128]
    float* red2 = red + 2 * AQ;       // [2][128]

    const int tid  = threadIdx.x;
    const int lane = tid & 31;
    const int wid  = tid >> 5;
    const int gid  = lane >> 2;
    const int tig  = lane & 3;
    const int sm_r = wid * 16;         // this warp's query rows
    const int bh = blockIdx.y;
    const int q0 = blockIdx.x * AQ;

    const float* Qp = Qg + (size_t)bh * Tt * HD;
    const float* Kp = Kg + (size_t)bh * Tt * HD;
    const float* Vp = Vg + (size_t)bh * Tt * HD;

    // Load Q tile [128][128] -> Qs[q][d] (tf32-rounded)
#pragma unroll
    for (int l = 0; l < 16; l++) {
        int f = tid + l * 256;
        int r = f >> 5;
        int c = (f & 31) * 4;
        float4 v = *(const float4*)&Qp[(size_t)(q0 + r) * HD + c];
        uint4 t;
        t.x = f2tf32(v.x); t.y = f2tf32(v.y);
        t.z = f2tf32(v.z); t.w = f2tf32(v.w);
        *(uint4*)&Qs[r * QS2 + c] = t;
    }
    if (tid < AQ) {
        rowm[tid] = -1e30f;
        rowl[tid] = 0.f;
    }

    // softmax mapping: 2 groups x 128 columns
    const int sg = tid >> 7;    // 0..1
    const int sq = tid & 127;   // query column

    float oacc[16][4];
#pragma unroll
    for (int i = 0; i < 16; i++)
#pragma unroll
        for (int q = 0; q < 4; q++) oacc[i][q] = 0.f;

    const int ntiles = 2 * blockIdx.x + 2;

#pragma unroll 1
    for (int kt = 0; kt < ntiles; kt++) {
        const int k0 = kt * 64;
        // Load K, V tiles [64][128]
#pragma unroll
        for (int l = 0; l < 8; l++) {
            int f = tid + l * 256;
            int r = f >> 5;
            int c = (f & 31) * 4;
            float4 kv = *(const float4*)&Kp[(size_t)(k0 + r) * HD + c];
            uint4 tk;
            tk.x = f2tf32(kv.x); tk.y = f2tf32(kv.y);
            tk.z = f2tf32(kv.z); tk.w = f2tf32(kv.w);
            *(uint4*)&Ks[r * KS2 + c] = tk;
            float4 vv = *(const float4*)&Vp[(size_t)(k0 + r) * HD + c];
            uint4 tv;
            tv.x = f2tf32(vv.x); tv.y = f2tf32(vv.y);
            tv.z = f2tf32(vv.z); tv.w = f2tf32(vv.w);
            *(uint4*)&Vs[r * VS2 + c] = tv;
        }
        __syncthreads();

        // ---- S = Q K^T (warp: 16 rows x 64 keys, reduce over d=128) ----
        float sacc[8][4];
#pragma unroll
        for (int nt = 0; nt < 8; nt++)
#pragma unroll
            for (int q = 0; q < 4; q++) sacc[nt][q] = 0.f;

#pragma unroll
        for (int ks = 0; ks < 16; ks++) {
            const int kk = ks * 8;
            uint32_t af[4];
            const int row = sm_r + gid;
            af[0] = __float_as_uint(Qs[row * QS2 + kk + tig]);
            af[1] = __float_as_uint(Qs[(row + 8) * QS2 + kk + tig]);
            af[2] = __float_as_uint(Qs[row * QS2 + kk + tig + 4]);
            af[3] = __float_as_uint(Qs[(row + 8) * QS2 + kk + tig + 4]);
#pragma unroll
            for (int nt = 0; nt < 8; nt++) {
                const int col = nt * 8 + gid;  // key index
                uint32_t bf[2];
                bf[0] = __float_as_uint(Ks[col * KS2 + kk + tig]);
                bf[1] = __float_as_uint(Ks[col * KS2 + kk + tig + 4]);
                mma_16n8k8_tf32(sacc[nt], af, bf);
            }
        }
        // scale + causal mask, store transposed into Ss[k][q]
#pragma unroll
        for (int nt = 0; nt < 8; nt++) {
            const int kb = nt * 8 + 2 * tig;
            const int kg = k0 + kb;
            const int qg = q0 + sm_r + gid;
            float v0 = sacc[nt][0] * SCALE; if (kg > qg)         v0 = -1e30f;
            float v1 = sacc[nt][1] * SCALE; if (kg + 1 > qg)     v1 = -1e30f;
            float v2 = sacc[nt][2] * SCALE; if (kg > qg + 8)     v2 = -1e30f;
            float v3 = sacc[nt][3] * SCALE; if (kg + 1 > qg + 8) v3 = -1e30f;
            Ss[kb * SS2 + sm_r + gid]           = v0;
            Ss[(kb + 1) * SS2 + sm_r + gid]     = v1;
            Ss[kb * SS2 + sm_r + gid + 8]       = v2;
            Ss[(kb + 1) * SS2 + sm_r + gid + 8] = v3;
        }
        __syncthreads();

        // ---- online softmax: 2 threads per query column, 32 keys each ----
        float pm = -1e30f;
        for (int kk = sg * 32; kk < sg * 32 + 32; kk++)
            pm = fmaxf(pm, Ss[kk * SS2 + sq]);
        red[sg * AQ + sq] = pm;
        __syncthreads();

        float mt = fmaxf(red[sq], red[AQ + sq]);
        float mo = rowm[sq];
        float mn = fmaxf(mo, mt);
        float ps = 0.f;
        for (int kk = sg * 32; kk < sg * 32 + 32; kk++) {
            float p = __expf(Ss[kk * SS2 + sq] - mn);
            Ss[kk * SS2 + sq] = p;
            ps += p;
        }
        red2[sg * AQ + sq] = ps;
        __syncthreads();

        if (sg == 0) {
            float ls = red2[sq] + red2[AQ + sq];
            float cf = __expf(mo - mn);
            corr[sq] = cf;
            rowm[sq] = mn;
            rowl[sq] = rowl[sq] * cf + ls;
        }
        __syncthreads();

        // ---- O += P V  (warp: 16 rows x 128 d, reduce over keys=64) ----
        {
            const float cf0 = corr[sm_r + gid];
            const float cf1 = corr[sm_r + gid + 8];
#pragma unroll
            for (int nt = 0; nt < 16; nt++) {
                oacc[nt][0] *= cf0; oacc[nt][1] *= cf0;
                oacc[nt][2] *= cf1; oacc[nt][3] *= cf1;
            }
        }
#pragma unroll
        for (int ks = 0; ks < 8; ks++) {
            const int kk = ks * 8;
            uint32_t af[4];
            af[0] = __float_as_uint(Ss[(kk + tig) * SS2 + sm_r + gid]);
            af[1] = __float_as_uint(Ss[(kk + tig) * SS2 + sm_r + gid + 8]);
            af[2] = __float_as_uint(Ss[(kk + tig + 4) * SS2 + sm_r + gid]);
            af[3] = __float_as_uint(Ss[(kk + tig + 4) * SS2 + sm_r + gid + 8]);
#pragma unroll
            for (int nt = 0; nt < 16; nt++) {
                const int col = nt * 8 + gid;  // d index
                uint32_t bf[2];
                bf[0] = __float_as_uint(Vs[(kk + tig) * VS2 + col]);
                bf[1] = __float_as_uint(Vs[(kk + tig + 4) * VS2 + col]);
                mma_16n8k8_tf32(oacc[nt], af, bf);
            }
        }
        __syncthreads();
    }

    // ---- epilogue: normalize, write ctx[b, t, h*HD + d] ----
    const int b = bh >> 4;
    const int h = bh & 15;
    const float inv0 = 1.f / rowl[sm_r + gid];
    const float inv1 = 1.f / rowl[sm_r + gid + 8];
    const int t0 = q0 + sm_r + gid;
    const int t1 = t0 + 8;
#pragma unroll
    for (int nt = 0; nt < 16; nt++) {
        const int d = nt * 8 + tig * 2;
        float2 lo = {oacc[nt][0] * inv0, oacc[nt][1] * inv0};
        float2 hi = {oacc[nt][2] * inv1, oacc[nt][3] * inv1};
        *(float2*)&ctx[((size_t)b * Tt + t0) * Dd + h * HD + d] = lo;
        *(float2*)&ctx[((size_t)b * Tt + t1) * Dd + h * HD + d] = hi;
    }
}

// ---------------------------------------------------------------------------
extern "C" void kernel_launch(void* const* d_in, const int* in_sizes, int n_in,
                              void* d_out, int out_size)
{
    const float* X   = (const float*)d_in[0];
    // d_in[1] = mask (exactly causal; applied analytically)
    const float* wq  = (const float*)d_in[2];
    const float* bq  = (const float*)d_in[3];
    const float* wk  = (const float*)d_in[4];
    const float* bk  = (const float*)d_in[5];
    const float* wv  = (const float*)d_in[6];
    const float* bv  = (const float*)d_in[7];
    const float* wo  = (const float*)d_in[8];
    const float* bo  = (const float*)d_in[9];
    float* out = (float*)d_out;

    float *Qb, *Kb, *Vb, *Cb;
    cudaGetSymbolAddress((void**)&Qb, g_Q);
    cudaGetSymbolAddress((void**)&Kb, g_K);
    cudaGetSymbolAddress((void**)&Vb, g_V);
    cudaGetSymbolAddress((void**)&Cb, g_ctx);

    cudaFuncSetAttribute(attn_kernel,
                         cudaFuncAttributeMaxDynamicSharedMemorySize,
                         ATTN_SMEM_BYTES);
    cudaFuncSetAttribute(tc_gemm<0>,
                         cudaFuncAttributeMaxDynamicSharedMemorySize, GSMEM2);
    cudaFuncSetAttribute(tc_gemm<1>,
                         cudaFuncAttributeMaxDynamicSharedMemorySize, GSMEM2);

    dim3 ggrid(Dd / GBN, Mrows / GBM);  // (16, 64)

    tc_gemm<1><<<ggrid, 256, GSMEM2>>>(X, wq, bq, Qb);
    tc_gemm<1><<<ggrid, 256, GSMEM2>>>(X, wk, bk, Kb);
    tc_gemm<1><<<ggrid, 256, GSMEM2>>>(X, wv, bv, Vb);

    dim3 agrid(Tt / AQ, Bb * Hh);       // (16, 64)
    attn_kernel<<<agrid, 256, ATTN_SMEM_BYTES>>>(Qb, Kb, Vb, Cb);

    tc_gemm<0><<<ggrid, 256, GSMEM2>>>(Cb, wo, bo, out);
}

// round 16
// speedup vs baseline: 5.8614x; 1.0258x over previous
#include <cuda_runtime.h>
#include <cuda_bf16.h>
#include <cstdint>

// ---------------------------------------------------------------------------
// Problem constants
// ---------------------------------------------------------------------------
constexpr int Bb = 4;
constexpr int Tt = 2048;
constexpr int Dd = 2048;
constexpr int Hh = 16;
constexpr int HD = 128;
constexpr int Mrows = Bb * Tt;  // 8192
constexpr float SCALE = 0.08838834764831845f;  // 1/sqrt(128)

// Scratch (device globals; no allocation allowed)
__device__ float g_Q[(size_t)Bb * Tt * Dd];
__device__ float g_K[(size_t)Bb * Tt * Dd];
__device__ float g_V[(size_t)Bb * Tt * Dd];
__device__ float g_ctx[(size_t)Bb * Tt * Dd];

// ---------------------------------------------------------------------------
// helpers
// ---------------------------------------------------------------------------
__device__ __forceinline__ uint32_t smem_u32(const void* p) {
    uint32_t a;
    asm("{ .reg .u64 t; cvta.to.shared.u64 t, %1; cvt.u32.u64 %0, t; }"
        : "=r"(a) : "l"(p));
    return a;
}

__device__ __forceinline__ uint32_t f2tf32(float x) {
    uint32_t r;
    asm("cvt.rna.tf32.f32 %0, %1;" : "=r"(r) : "f"(x));
    return r;
}

__device__ __forceinline__ void mma_16n8k8_tf32(
    float c[4], const uint32_t a[4], const uint32_t b[2])
{
    asm volatile(
        "mma.sync.aligned.m16n8k8.row.col.f32.tf32.tf32.f32 "
        "{%0,%1,%2,%3}, {%4,%5,%6,%7}, {%8,%9}, {%0,%1,%2,%3};"
        : "+f"(c[0]), "+f"(c[1]), "+f"(c[2]), "+f"(c[3])
        : "r"(a[0]), "r"(a[1]), "r"(a[2]), "r"(a[3]),
          "r"(b[0]), "r"(b[1]));
}

__device__ __forceinline__ void cp_async16(uint32_t saddr, const void* gptr) {
    asm volatile("cp.async.cg.shared.global [%0], [%1], 16;"
                 :: "r"(saddr), "l"(gptr));
}
#define CP_COMMIT() asm volatile("cp.async.commit_group;" ::: "memory")
#define CP_WAIT1()  asm volatile("cp.async.wait_group 1;" ::: "memory")
#define CP_WAIT0()  asm volatile("cp.async.wait_group 0;" ::: "memory")

// ---------------------------------------------------------------------------
// tf32 mma.sync GEMM v3: C[M,N] = A[M,K] @ W[K,N] + bias
// Block 128x128x32, 256 threads = 8 warps (2x4), warp = 64x32.
// 3-stage cp.async pipeline; smem holds raw fp32; cvt.rna at fragment load
// (bit-identical tf32 inputs & MMA order vs R12/R15).
// ---------------------------------------------------------------------------
constexpr int GBM = 128, GBN = 128, GBK = 32, GKD = 2048;
constexpr int KT_ITERS = GKD / GBK;  // 64
constexpr int AS_STRIDE = 36;        // 144 B rows (16B aligned)
constexpr int BS_STRIDE = 136;       // 544 B rows (16B aligned)
constexpr int AS_TILE = GBM * AS_STRIDE;   // 4608 floats
constexpr int BS_TILE = GBK * BS_STRIDE;   // 4352 floats
constexpr int STAGE_FLOATS = AS_TILE + BS_TILE;  // 8960
constexpr int GSMEM3 = 3 * STAGE_FLOATS * 4;     // 107520 B

template <int MODE>
__global__ __launch_bounds__(256) void tc_gemm(
    const float* __restrict__ A, const float* __restrict__ W,
    const float* __restrict__ bias, float* __restrict__ Cout)
{
    extern __shared__ float gsm[];
    const uint32_t sbase = smem_u32(gsm);

    const int tid  = threadIdx.x;
    const int lane = tid & 31;
    const int wid  = tid >> 5;
    const int gid  = lane >> 2;
    const int tig  = lane & 3;
    const int wm   = (wid >> 2) * 64;
    const int wn   = (wid & 3) * 32;
    const int m0   = blockIdx.y * GBM;
    const int n0   = blockIdx.x * GBN;

    // per-thread fixed copy coordinates
    const int ar[4] = {(tid) >> 3, (tid + 256) >> 3, (tid + 512) >> 3, (tid + 768) >> 3};
    const int ac = (tid & 7) * 4;
    const int br[4] = {(tid) >> 5, (tid + 256) >> 5, (tid + 512) >> 5, (tid + 768) >> 5};
    const int bc = (tid & 31) * 4;

    auto copy_stage = [&](int kt, int buf) {
        const int k0 = kt * GBK;
        const uint32_t abase = sbase + (uint32_t)buf * STAGE_FLOATS * 4;
        const uint32_t bbase = abase + AS_TILE * 4;
#pragma unroll
        for (int l = 0; l < 4; l++)
            cp_async16(abase + (ar[l] * AS_STRIDE + ac) * 4,
                       &A[(size_t)(m0 + ar[l]) * GKD + k0 + ac]);
#pragma unroll
        for (int l = 0; l < 4; l++)
            cp_async16(bbase + (br[l] * BS_STRIDE + bc) * 4,
                       &W[(size_t)(k0 + br[l]) * Dd + n0 + bc]);
        CP_COMMIT();
    };

    float acc[4][4][4];
#pragma unroll
    for (int i = 0; i < 4; i++)
#pragma unroll
        for (int j = 0; j < 4; j++)
#pragma unroll
            for (int q = 0; q < 4; q++) acc[i][j][q] = 0.f;

    copy_stage(0, 0);
    copy_stage(1, 1);

#pragma unroll 1
    for (int kt = 0; kt < KT_ITERS; kt++) {
        if (kt < KT_ITERS - 1) { CP_WAIT1(); } else { CP_WAIT0(); }
        __syncthreads();   // stage kt visible to all; also fences kt-1 readers

        if (kt + 2 < KT_ITERS) copy_stage(kt + 2, (kt + 2) % 3);

        const float* As = gsm + (kt % 3) * STAGE_FLOATS;
        const float* Bs = As + AS_TILE;

#pragma unroll
        for (int ks = 0; ks < 4; ks++) {
            const int kk = ks * 8;
            uint32_t af[4][4];
#pragma unroll
            for (int mt = 0; mt < 4; mt++) {
                int row = wm + mt * 16 + gid;
                af[mt][0] = f2tf32(As[row * AS_STRIDE + kk + tig]);
                af[mt][1] = f2tf32(As[(row + 8) * AS_STRIDE + kk + tig]);
                af[mt][2] = f2tf32(As[row * AS_STRIDE + kk + tig + 4]);
                af[mt][3] = f2tf32(As[(row + 8) * AS_STRIDE + kk + tig + 4]);
            }
            uint32_t bf[4][2];
#pragma unroll
            for (int nt = 0; nt < 4; nt++) {
                int col = wn + nt * 8 + gid;
                bf[nt][0] = f2tf32(Bs[(kk + tig) * BS_STRIDE + col]);
                bf[nt][1] = f2tf32(Bs[(kk + tig + 4) * BS_STRIDE + col]);
            }
#pragma unroll
            for (int mt = 0; mt < 4; mt++)
#pragma unroll
                for (int nt = 0; nt < 4; nt++)
                    mma_16n8k8_tf32(acc[mt][nt], af[mt], bf[nt]);
        }
        __syncthreads();   // all readers done before buf (kt+3)%3 == (kt)%3 reuse
    }

#pragma unroll
    for (int mt = 0; mt < 4; mt++) {
#pragma unroll
        for (int nt = 0; nt < 4; nt++) {
            int row = m0 + wm + mt * 16 + gid;
            int col = n0 + wn + nt * 8 + tig * 2;
            float bx = bias[col], by = bias[col + 1];
            float2 lo = {acc[mt][nt][0] + bx, acc[mt][nt][1] + by};
            float2 hi = {acc[mt][nt][2] + bx, acc[mt][nt][3] + by};
            if (MODE == 0) {
                *(float2*)&Cout[(size_t)row * Dd + col] = lo;
                *(float2*)&Cout[(size_t)(row + 8) * Dd + col] = hi;
            } else {
                const int h = col >> 7, hd = col & 127;
                int b = row >> 11, t = row & 2047;
                *(float2*)&Cout[(((size_t)b * Hh + h) * Tt + t) * HD + hd] = lo;
                b = (row + 8) >> 11; t = (row + 8) & 2047;
                *(float2*)&Cout[(((size_t)b * Hh + h) * Tt + t) * HD + hd] = hi;
            }
        }
    }
}

// ---------------------------------------------------------------------------
// Flash attention, tf32 mma.sync, 128-query blocks x 64-key tiles.
// (unchanged from R15 passing version — byte-identical)
// ---------------------------------------------------------------------------
constexpr int AQ = 128;
constexpr int QS2 = 132;
constexpr int KS2 = 132;
constexpr int VS2 = 136;
constexpr int SS2 = 132;
constexpr int ATTN_SMEM_FLOATS =
    AQ * QS2 + 64 * KS2 + 64 * VS2 + 64 * SS2 + AQ * 3 + 2 * AQ * 2;
constexpr int ATTN_SMEM_BYTES = ATTN_SMEM_FLOATS * 4;  // ~169.6 KB

__global__ __launch_bounds__(256) void attn_kernel(
    const float* __restrict__ Qg, const float* __restrict__ Kg,
    const float* __restrict__ Vg, float* __restrict__ ctx)
{
    extern __shared__ float sm[];
    float* Qs   = sm;
    float* Ks   = Qs + AQ * QS2;
    float* Vs   = Ks + 64 * KS2;
    float* Ss   = Vs + 64 * VS2;
    float* rowm = Ss + 64 * SS2;
    float* rowl = rowm + AQ;
    float* corr = rowl + AQ;
    float* red  = corr + AQ;
    float* red2 = red + 2 * AQ;

    const int tid  = threadIdx.x;
    const int lane = tid & 31;
    const int wid  = tid >> 5;
    const int gid  = lane >> 2;
    const int tig  = lane & 3;
    const int sm_r = wid * 16;
    const int bh = blockIdx.y;
    const int q0 = blockIdx.x * AQ;

    const float* Qp = Qg + (size_t)bh * Tt * HD;
    const float* Kp = Kg + (size_t)bh * Tt * HD;
    const float* Vp = Vg + (size_t)bh * Tt * HD;

#pragma unroll
    for (int l = 0; l < 16; l++) {
        int f = tid + l * 256;
        int r = f >> 5;
        int c = (f & 31) * 4;
        float4 v = *(const float4*)&Qp[(size_t)(q0 + r) * HD + c];
        uint4 t;
        t.x = f2tf32(v.x); t.y = f2tf32(v.y);
        t.z = f2tf32(v.z); t.w = f2tf32(v.w);
        *(uint4*)&Qs[r * QS2 + c] = t;
    }
    if (tid < AQ) {
        rowm[tid] = -1e30f;
        rowl[tid] = 0.f;
    }

    const int sg = tid >> 7;
    const int sq = tid & 127;

    float oacc[16][4];
#pragma unroll
    for (int i = 0; i < 16; i++)
#pragma unroll
        for (int q = 0; q < 4; q++) oacc[i][q] = 0.f;

    const int ntiles = 2 * blockIdx.x + 2;

#pragma unroll 1
    for (int kt = 0; kt < ntiles; kt++) {
        const int k0 = kt * 64;
#pragma unroll
        for (int l = 0; l < 8; l++) {
            int f = tid + l * 256;
            int r = f >> 5;
            int c = (f & 31) * 4;
            float4 kv = *(const float4*)&Kp[(size_t)(k0 + r) * HD + c];
            uint4 tk;
            tk.x = f2tf32(kv.x); tk.y = f2tf32(kv.y);
            tk.z = f2tf32(kv.z); tk.w = f2tf32(kv.w);
            *(uint4*)&Ks[r * KS2 + c] = tk;
            float4 vv = *(const float4*)&Vp[(size_t)(k0 + r) * HD + c];
            uint4 tv;
            tv.x = f2tf32(vv.x); tv.y = f2tf32(vv.y);
            tv.z = f2tf32(vv.z); tv.w = f2tf32(vv.w);
            *(uint4*)&Vs[r * VS2 + c] = tv;
        }
        __syncthreads();

        float sacc[8][4];
#pragma unroll
        for (int nt = 0; nt < 8; nt++)
#pragma unroll
            for (int q = 0; q < 4; q++) sacc[nt][q] = 0.f;

#pragma unroll
        for (int ks = 0; ks < 16; ks++) {
            const int kk = ks * 8;
            uint32_t af[4];
            const int row = sm_r + gid;
            af[0] = __float_as_uint(Qs[row * QS2 + kk + tig]);
            af[1] = __float_as_uint(Qs[(row + 8) * QS2 + kk + tig]);
            af[2] = __float_as_uint(Qs[row * QS2 + kk + tig + 4]);
            af[3] = __float_as_uint(Qs[(row + 8) * QS2 + kk + tig + 4]);
#pragma unroll
            for (int nt = 0; nt < 8; nt++) {
                const int col = nt * 8 + gid;
                uint32_t bf[2];
                bf[0] = __float_as_uint(Ks[col * KS2 + kk + tig]);
                bf[1] = __float_as_uint(Ks[col * KS2 + kk + tig + 4]);
                mma_16n8k8_tf32(sacc[nt], af, bf);
            }
        }
#pragma unroll
        for (int nt = 0; nt < 8; nt++) {
            const int kb = nt * 8 + 2 * tig;
            const int kg = k0 + kb;
            const int qg = q0 + sm_r + gid;
            float v0 = sacc[nt][0] * SCALE; if (kg > qg)         v0 = -1e30f;
            float v1 = sacc[nt][1] * SCALE; if (kg + 1 > qg)     v1 = -1e30f;
            float v2 = sacc[nt][2] * SCALE; if (kg > qg + 8)     v2 = -1e30f;
            float v3 = sacc[nt][3] * SCALE; if (kg + 1 > qg + 8) v3 = -1e30f;
            Ss[kb * SS2 + sm_r + gid]           = v0;
            Ss[(kb + 1) * SS2 + sm_r + gid]     = v1;
            Ss[kb * SS2 + sm_r + gid + 8]       = v2;
            Ss[(kb + 1) * SS2 + sm_r + gid + 8] = v3;
        }
        __syncthreads();

        float pm = -1e30f;
        for (int kk = sg * 32; kk < sg * 32 + 32; kk++)
            pm = fmaxf(pm, Ss[kk * SS2 + sq]);
        red[sg * AQ + sq] = pm;
        __syncthreads();

        float mt = fmaxf(red[sq], red[AQ + sq]);
        float mo = rowm[sq];
        float mn = fmaxf(mo, mt);
        float ps = 0.f;
        for (int kk = sg * 32; kk < sg * 32 + 32; kk++) {
            float p = __expf(Ss[kk * SS2 + sq] - mn);
            Ss[kk * SS2 + sq] = p;
            ps += p;
        }
        red2[sg * AQ + sq] = ps;
        __syncthreads();

        if (sg == 0) {
            float ls = red2[sq] + red2[AQ + sq];
            float cf = __expf(mo - mn);
            corr[sq] = cf;
            rowm[sq] = mn;
            rowl[sq] = rowl[sq] * cf + ls;
        }
        __syncthreads();

        {
            const float cf0 = corr[sm_r + gid];
            const float cf1 = corr[sm_r + gid + 8];
#pragma unroll
            for (int nt = 0; nt < 16; nt++) {
                oacc[nt][0] *= cf0; oacc[nt][1] *= cf0;
                oacc[nt][2] *= cf1; oacc[nt][3] *= cf1;
            }
        }
#pragma unroll
        for (int ks = 0; ks < 8; ks++) {
            const int kk = ks * 8;
            uint32_t af[4];
            af[0] = __float_as_uint(Ss[(kk + tig) * SS2 + sm_r + gid]);
            af[1] = __float_as_uint(Ss[(kk + tig) * SS2 + sm_r + gid + 8]);
            af[2] = __float_as_uint(Ss[(kk + tig + 4) * SS2 + sm_r + gid]);
            af[3] = __float_as_uint(Ss[(kk + tig + 4) * SS2 + sm_r + gid + 8]);
#pragma unroll
            for (int nt = 0; nt < 16; nt++) {
                const int col = nt * 8 + gid;
                uint32_t bf[2];
                bf[0] = __float_as_uint(Vs[(kk + tig) * VS2 + col]);
                bf[1] = __float_as_uint(Vs[(kk + tig + 4) * VS2 + col]);
                mma_16n8k8_tf32(oacc[nt], af, bf);
            }
        }
        __syncthreads();
    }

    const int b = bh >> 4;
    const int h = bh & 15;
    const float inv0 = 1.f / rowl[sm_r + gid];
    const float inv1 = 1.f / rowl[sm_r + gid + 8];
    const int t0 = q0 + sm_r + gid;
    const int t1 = t0 + 8;
#pragma unroll
    for (int nt = 0; nt < 16; nt++) {
        const int d = nt * 8 + tig * 2;
        float2 lo = {oacc[nt][0] * inv0, oacc[nt][1] * inv0};
        float2 hi = {oacc[nt][2] * inv1, oacc[nt][3] * inv1};
        *(float2*)&ctx[((size_t)b * Tt + t0) * Dd + h * HD + d] = lo;
        *(float2*)&ctx[((size_t)b * Tt + t1) * Dd + h * HD + d] = hi;
    }
}

// ---------------------------------------------------------------------------
extern "C" void kernel_launch(void* const* d_in, const int* in_sizes, int n_in,
                              void* d_out, int out_size)
{
    const float* X   = (const float*)d_in[0];
    // d_in[1] = mask (exactly causal; applied analytically)
    const float* wq  = (const float*)d_in[2];
    const float* bq  = (const float*)d_in[3];
    const float* wk  = (const float*)d_in[4];
    const float* bk  = (const float*)d_in[5];
    const float* wv  = (const float*)d_in[6];
    const float* bv  = (const float*)d_in[7];
    const float* wo  = (const float*)d_in[8];
    const float* bo  = (const float*)d_in[9];
    float* out = (float*)d_out;

    float *Qb, *Kb, *Vb, *Cb;
    cudaGetSymbolAddress((void**)&Qb, g_Q);
    cudaGetSymbolAddress((void**)&Kb, g_K);
    cudaGetSymbolAddress((void**)&Vb, g_V);
    cudaGetSymbolAddress((void**)&Cb, g_ctx);

    cudaFuncSetAttribute(attn_kernel,
                         cudaFuncAttributeMaxDynamicSharedMemorySize,
                         ATTN_SMEM_BYTES);
    cudaFuncSetAttribute(tc_gemm<0>,
                         cudaFuncAttributeMaxDynamicSharedMemorySize, GSMEM3);
    cudaFuncSetAttribute(tc_gemm<1>,
                         cudaFuncAttributeMaxDynamicSharedMemorySize, GSMEM3);

    dim3 ggrid(Dd / GBN, Mrows / GBM);  // (16, 64)

    tc_gemm<1><<<ggrid, 256, GSMEM3>>>(X, wq, bq, Qb);
    tc_gemm<1><<<ggrid, 256, GSMEM3>>>(X, wk, bk, Kb);
    tc_gemm<1><<<ggrid, 256, GSMEM3>>>(X, wv, bv, Vb);

    dim3 agrid(Tt / AQ, Bb * Hh);       // (16, 64)
    attn_kernel<<<agrid, 256, ATTN_SMEM_BYTES>>>(Qb, Kb, Vb, Cb);

    tc_gemm<0><<<ggrid, 256, GSMEM3>>>(Cb, wo, bo, out);
}